// round 16
// baseline (speedup 1.0000x reference)
#include <cuda_runtime.h>
#include <cuda_bf16.h>
#include <cstdint>

#define N_CELLS 50000
#define DEG 32
#define D 64
#define NEG_SLOPE 0.2f
#define ROWS_CTA 32          // 8 warps x 4 rows
#define XPAD 68              // padded row stride (floats) = 34 u64

typedef unsigned long long u64;

// ---- packed f32x2 helpers (lane-wise .rn == scalar ops, bit-exact) ----
__device__ __forceinline__ u64 packdup(float v) {
    u64 r; asm("mov.b64 %0, {%1, %1};" : "=l"(r) : "f"(v)); return r;
}
__device__ __forceinline__ void unpack2(u64 v, float& a, float& b) {
    asm("mov.b64 {%0, %1}, %2;" : "=f"(a), "=f"(b) : "l"(v));
}
__device__ __forceinline__ u64 fma2(u64 a, u64 b, u64 c) {
    u64 r; asm("fma.rn.f32x2 %0, %1, %2, %3;" : "=l"(r) : "l"(a), "l"(b), "l"(c)); return r;
}
__device__ __forceinline__ u64 mul2(u64 a, u64 b) {
    u64 r; asm("mul.rn.f32x2 %0, %1, %2;" : "=l"(r) : "l"(a), "l"(b)); return r;
}
__device__ __forceinline__ u64 add2(u64 a, u64 b) {
    u64 r; asm("add.rn.f32x2 %0, %1, %2;" : "=l"(r) : "l"(a), "l"(b)); return r;
}

// -------- Kernel 1: warp = 4 rows, thread = 8 cols (4 packed accs).
// 12500 warps chip-wide (21/SMSP) with warp-uniform-per-cg W reads
// (8 distinct 16B lines = 1 conflict-free wavefront, 4-way broadcast).
// Bit-exact orders (validated R9/R12/R13):
//   gemm: per column pair, sequential fused FMA2 over k=0..63 in one thread
//   gemv: width-8 strided fma partials over ascending col-pairs, AddReduce
//         halving ((p0+p4)+(p2+p6)) + ((p1+p5)+(p3+p7)), one thread per row
__global__ void __launch_bounds__(256) gemm_proj_kernel(
    const float* __restrict__ x,     // [N, 64]
    const float* __restrict__ W,     // [64, 64]
    const float* __restrict__ a0,    // [128, 1]
    float* __restrict__ msg,         // [N, 64]
    float* __restrict__ ns,          // [N]
    float* __restrict__ nd,          // [N]
    int n)
{
    __shared__ __align__(16) float Wsh[D * D];            // 16 KB row-major [k][j]
    __shared__ __align__(16) float ash[2 * D];
    __shared__ __align__(16) float xsh[ROWS_CTA * XPAD];  // x rows, then acc staging

    const int tid = threadIdx.x;
    const int base = blockIdx.x * ROWS_CTA;
    const int rows_here = min(ROWS_CTA, n - base);

    for (int i = tid; i < D * D; i += 256) Wsh[i] = W[i];
    if (tid < 2 * D) ash[tid] = a0[tid];
    for (int idx = tid; idx < rows_here * D; idx += 256) {
        xsh[(idx >> 6) * XPAD + (idx & 63)] = x[(size_t)base * D + idx];
    }
    __syncthreads();

    const int lane = tid & 31;
    const int rr = (tid >> 3) & 3;       // row within warp: lane>>3
    const int warp = tid >> 5;
    const int lrow = warp * 4 + rr;      // row slot within CTA (0..31)
    const int cg = lane & 7;             // col group: pairs jp = cg*4 .. cg*4+3
    const bool active = lrow < rows_here;

    u64 acc[4] = {0ull, 0ull, 0ull, 0ull};
    if (active) {
        const float* __restrict__ xrow = xsh + lrow * XPAD;
#pragma unroll
        for (int kc = 0; kc < 16; kc++) {
            const float4 xv = *(const float4*)(xrow + kc * 4);   // 4 distinct/warp
            const float xk[4] = {xv.x, xv.y, xv.z, xv.w};
#pragma unroll
            for (int kk = 0; kk < 4; kk++) {
                const u64 xd = packdup(xk[kk]);
                const ulonglong2* __restrict__ wr =
                    (const ulonglong2*)(Wsh + (kc * 4 + kk) * D + cg * 8);
                const ulonglong2 wv = *wr;          // 8x16B contiguous: 1 wavefront
                acc[0] = fma2(xd, wv.x, acc[0]);
                acc[1] = fma2(xd, wv.y, acc[1]);
                const ulonglong2 wv2 = wr[1];
                acc[2] = fma2(xd, wv2.x, acc[2]);
                acc[3] = fma2(xd, wv2.y, acc[3]);
            }
        }

        // msg store straight from registers (coalesced 128B lines per warp quarter)
        ulonglong2* __restrict__ mo =
            (ulonglong2*)(msg + (size_t)(base + lrow) * D + cg * 8);
        ulonglong2 v0; v0.x = acc[0]; v0.y = acc[1];
        ulonglong2 v1; v1.x = acc[2]; v1.y = acc[3];
        mo[0] = v0;
        mo[1] = v1;

        // stage accs into this row's own xsh slice (warp-private: no sync needed
        // between this warp's mainloop reads and its own staging writes)
        u64* __restrict__ stage = (u64*)xsh + lrow * (XPAD / 2) + cg * 4;
        stage[0] = acc[0]; stage[1] = acc[1]; stage[2] = acc[2]; stage[3] = acc[3];
    }
    __syncthreads();   // gemv reads rows staged by other warps

    // gemv: one thread per row, exact R9/R12 order over ascending pairs
    if (tid < rows_here) {
        const u64* __restrict__ ms2 = (const u64*)xsh + tid * (XPAD / 2);
        const u64* __restrict__ as2 = (const u64*)ash;
        const u64* __restrict__ ad2 = (const u64*)(ash + D);
        u64 pps[4] = {0ull, 0ull, 0ull, 0ull};
        u64 ppd[4] = {0ull, 0ull, 0ull, 0ull};
#pragma unroll
        for (int jp = 0; jp < 32; jp++) {
            const u64 mv = ms2[jp];
            pps[jp & 3] = fma2(mv, as2[jp], pps[jp & 3]);
            ppd[jp & 3] = fma2(mv, ad2[jp], ppd[jp & 3]);
        }
        {
            const u64 q01 = add2(pps[0], pps[2]);
            const u64 q23 = add2(pps[1], pps[3]);
            const u64 rr2 = add2(q01, q23);
            float lo, hi; unpack2(rr2, lo, hi);
            ns[base + tid] = __fadd_rn(lo, hi);
        }
        {
            const u64 q01 = add2(ppd[0], ppd[2]);
            const u64 q23 = add2(ppd[1], ppd[3]);
            const u64 rr2 = add2(q01, q23);
            float lo, hi; unpack2(rr2, lo, hi);
            nd[base + tid] = __fadd_rn(lo, hi);
        }
    }
}

// -------- Kernel 2: per-row edge attention + gather-aggregate. One warp per row.
// At the practical LTS cap (~410MB of L2 gathers ≈ 36µs) — unchanged from R12.
__global__ void __launch_bounds__(256) gat_aggregate_kernel(
    const float* __restrict__ msg,   // [N, 64]
    const float* __restrict__ ns,    // [N]
    const float* __restrict__ nd,    // [N]
    const int*   __restrict__ cols,  // [N*32]
    const float* __restrict__ nv,    // [N*32]
    float* __restrict__ out,         // [N, 64]
    int n)
{
    __shared__ float2 cw[8][DEG];    // per-warp staged {col, wgt}

    const int wid = threadIdx.x >> 5;
    const int lane = threadIdx.x & 31;
    const int row = blockIdx.x * 8 + wid;
    if (row >= n) return;

    const int eidx = row * DEG + lane;
    const int col = cols[eidx];

    float e = __fadd_rn(ns[row], __ldg(&nd[col]));
    e = (e >= 0.f) ? e : __fmul_rn(NEG_SLOPE, e);

    // row sum: strictly sequential in edge order
    float S = 0.f;
#pragma unroll
    for (int k = 0; k < DEG; k++)
        S = __fadd_rn(S, __shfl_sync(0xFFFFFFFFu, e, k));

    const float att = __fdiv_rn(e, S);
    const float wgt = __fmul_rn(nv[eidx], att);   // vals = nv * att

    cw[wid][lane] = make_float2(__int_as_float(col), wgt);
    __syncwarp();

    const u64* __restrict__ m2 = (const u64*)msg;  // packed col-pairs
    u64 acc = 0ull;
#pragma unroll
    for (int kb = 0; kb < DEG; kb += 8) {
        int c[8]; u64 w2[8];
#pragma unroll
        for (int i = 0; i < 8; i++) {
            const float2 t = cw[wid][kb + i];      // broadcast LDS.64
            c[i] = __float_as_int(t.x);
            w2[i] = packdup(t.y);
        }
        u64 m[8];
#pragma unroll
        for (int i = 0; i < 8; i++)
            m[i] = m2[(size_t)c[i] * (D / 2) + lane];
#pragma unroll
        for (int i = 0; i < 8; i++)
            acc = add2(acc, mul2(w2[i], m[i]));    // ascending edge order
    }
    float ax, ay; unpack2(acc, ax, ay);
    ax = fmaxf(ax, 0.f);
    ay = fmaxf(ay, 0.f);
    ((float2*)out)[(size_t)row * (D / 2) + lane] = make_float2(ax, ay);
}

// Scratch for intermediates (no cudaMalloc allowed)
__device__ float g_msg[N_CELLS * D];
__device__ float g_ns[N_CELLS];
__device__ float g_nd[N_CELLS];

extern "C" void kernel_launch(void* const* d_in, const int* in_sizes, int n_in,
                              void* d_out, int out_size) {
    const float* x    = (const float*)d_in[0];   // x_source [N,64]
    // d_in[1] = edge_rows (implicit: repeat(arange(N), 32)) — unused
    const int*   cols = (const int*)  d_in[2];   // edge_cols [N*32]
    const float* nv   = (const float*)d_in[3];   // neighborhood_values [N*32]
    const float* W0   = (const float*)d_in[4];   // [64,64]
    const float* a0   = (const float*)d_in[5];   // [128,1]
    float* out = (float*)d_out;

    float* msg; float* ns; float* nd;
    cudaGetSymbolAddress((void**)&msg, g_msg);
    cudaGetSymbolAddress((void**)&ns,  g_ns);
    cudaGetSymbolAddress((void**)&nd,  g_nd);

    const int n = N_CELLS;

    // Kernel 1: 32 rows per 256-thread CTA (warp = 4 rows, thread = 8 cols)
    int grid1 = (n + ROWS_CTA - 1) / ROWS_CTA;
    gemm_proj_kernel<<<grid1, 256>>>(x, W0, a0, msg, ns, nd, n);

    // Kernel 2: one warp per row, 8 rows per 256-thread block
    int grid2 = (n + 7) / 8;
    gat_aggregate_kernel<<<grid2, 256>>>(msg, ns, nd, cols, nv, out, n);
}

// round 17
// speedup vs baseline: 1.6397x; 1.6397x over previous
#include <cuda_runtime.h>
#include <cuda_bf16.h>
#include <cstdint>

#define N_CELLS 50000
#define DEG 32
#define D 64
#define NEG_SLOPE 0.2f
#define ROWS_CTA 64
#define XPAD 68   // padded row stride (floats): %4==0 for LDS.128 alignment

typedef unsigned long long u64;

// ---- packed f32x2 helpers (lane-wise .rn == scalar ops, bit-exact) ----
__device__ __forceinline__ u64 packdup(float v) {
    u64 r; asm("mov.b64 %0, {%1, %1};" : "=l"(r) : "f"(v)); return r;
}
__device__ __forceinline__ void unpack2(u64 v, float& a, float& b) {
    asm("mov.b64 {%0, %1}, %2;" : "=f"(a), "=f"(b) : "l"(v));
}
__device__ __forceinline__ u64 fma2(u64 a, u64 b, u64 c) {
    u64 r; asm("fma.rn.f32x2 %0, %1, %2, %3;" : "=l"(r) : "l"(a), "l"(b), "l"(c)); return r;
}
__device__ __forceinline__ u64 mul2(u64 a, u64 b) {
    u64 r; asm("mul.rn.f32x2 %0, %1, %2;" : "=l"(r) : "l"(a), "l"(b)); return r;
}
__device__ __forceinline__ u64 add2(u64 a, u64 b) {
    u64 r; asm("add.rn.f32x2 %0, %1, %2;" : "=l"(r) : "l"(a), "l"(b)); return r;
}

// -------- Kernel 1: thread-per-row (R13 shape, best measured), 64-thread CTAs
// for finer wave granularity (782 CTAs vs 391 -> tail waste 35% -> 5% of a wave).
// Bit-exact orders (validated R9/R12/R13):
//   gemm: per output element, sequential fused FMA over k=0..63 (f32x2 lanes)
//   gemv: width-8 strided fma partials, AddReduce halving
//         ((p0+p4)+(p2+p6)) + ((p1+p5)+(p3+p7))
__global__ void __launch_bounds__(64) gemm_proj_kernel(
    const float* __restrict__ x,     // [N, 64]
    const float* __restrict__ W,     // [64, 64]
    const float* __restrict__ a0,    // [128, 1]
    float* __restrict__ msg,         // [N, 64]
    float* __restrict__ ns,          // [N]
    float* __restrict__ nd,          // [N]
    int n)
{
    __shared__ __align__(16) float Wsh[D * D];            // 16 KB, row-major [k][j]
    __shared__ __align__(16) float ash[2 * D];
    __shared__ __align__(16) float xsh[ROWS_CTA * XPAD];  // x rows / acc staging

    const int tid = threadIdx.x;
    const int base = blockIdx.x * ROWS_CTA;
    const int rows_here = min(ROWS_CTA, n - base);

    for (int i = tid; i < D * D; i += 64) Wsh[i] = W[i];
    for (int i = tid; i < 2 * D; i += 64) ash[i] = a0[i];
    // coalesced x load -> padded smem rows
    for (int idx = tid; idx < rows_here * D; idx += 64) {
        xsh[(idx >> 6) * XPAD + (idx & 63)] = x[(size_t)base * D + idx];
    }
    __syncthreads();

    const bool active = tid < rows_here;
    u64 acc[32];
    if (active) {
#pragma unroll
        for (int m = 0; m < 32; m++) acc[m] = 0ull;

        // own row into registers (16B-aligned LDS.128)
        float4 xr[16];
        const float4* __restrict__ xrow = (const float4*)(xsh + tid * XPAD);
#pragma unroll
        for (int i = 0; i < 16; i++) xr[i] = xrow[i];

#pragma unroll
        for (int kc = 0; kc < 16; kc++) {
            const float xk[4] = {xr[kc].x, xr[kc].y, xr[kc].z, xr[kc].w};
#pragma unroll
            for (int kk = 0; kk < 4; kk++) {
                const u64 xd = packdup(xk[kk]);
                const ulonglong2* __restrict__ wr =
                    (const ulonglong2*)(Wsh + (kc * 4 + kk) * D);
#pragma unroll
                for (int m = 0; m < 16; m++) {
                    const ulonglong2 wv = wr[m];   // broadcast LDS.128
                    acc[2 * m]     = fma2(xd, wv.x, acc[2 * m]);
                    acc[2 * m + 1] = fma2(xd, wv.y, acc[2 * m + 1]);
                }
            }
        }

        // gemv (ns and nd), exact R9 order:
        // pp0={p0,p1} pp1={p2,p3} pp2={p4,p5} pp3={p6,p7}
        const u64* __restrict__ as2 = (const u64*)ash;
        const u64* __restrict__ ad2 = (const u64*)(ash + D);
        u64 pps[4] = {0ull, 0ull, 0ull, 0ull};
        u64 ppd[4] = {0ull, 0ull, 0ull, 0ull};
#pragma unroll
        for (int jp = 0; jp < 32; jp++) {
            pps[jp & 3] = fma2(acc[jp], as2[jp], pps[jp & 3]);
            ppd[jp & 3] = fma2(acc[jp], ad2[jp], ppd[jp & 3]);
        }
        {
            const u64 q01 = add2(pps[0], pps[2]);
            const u64 q23 = add2(pps[1], pps[3]);
            const u64 rr  = add2(q01, q23);
            float lo, hi; unpack2(rr, lo, hi);
            ns[base + tid] = __fadd_rn(lo, hi);
        }
        {
            const u64 q01 = add2(ppd[0], ppd[2]);
            const u64 q23 = add2(ppd[1], ppd[3]);
            const u64 rr  = add2(q01, q23);
            float lo, hi; unpack2(rr, lo, hi);
            nd[base + tid] = __fadd_rn(lo, hi);
        }
    }
    __syncthreads();   // all xsh reads complete

    // park acc rows back into xsh (same [r*XPAD .. r*XPAD+64) footprint)
    if (active) {
        u64* __restrict__ stage = (u64*)xsh + tid * (XPAD / 2);
#pragma unroll
        for (int m = 0; m < 32; m++) stage[m] = acc[m];
    }
    __syncthreads();

    // coalesced msg store (float4 sweep)
    {
        float4* __restrict__ dst4 = (float4*)(msg + (size_t)base * D);
        const int total4 = rows_here * (D / 4);
        for (int q = tid; q < total4; q += 64) {
            dst4[q] = *(const float4*)(xsh + (q >> 4) * XPAD + (q & 15) * 4);
        }
    }
}

// -------- Kernel 2: per-row edge attention + gather-aggregate. One warp per row.
// At the practical LTS cap (~410MB of L2 gathers ≈ 36µs) — byte-for-byte R13.
__global__ void __launch_bounds__(256) gat_aggregate_kernel(
    const float* __restrict__ msg,   // [N, 64]
    const float* __restrict__ ns,    // [N]
    const float* __restrict__ nd,    // [N]
    const int*   __restrict__ cols,  // [N*32]
    const float* __restrict__ nv,    // [N*32]
    float* __restrict__ out,         // [N, 64]
    int n)
{
    __shared__ float2 cw[8][DEG];    // per-warp staged {col, wgt}

    const int wid = threadIdx.x >> 5;
    const int lane = threadIdx.x & 31;
    const int row = blockIdx.x * 8 + wid;
    if (row >= n) return;

    const int eidx = row * DEG + lane;
    const int col = cols[eidx];

    float e = __fadd_rn(ns[row], __ldg(&nd[col]));
    e = (e >= 0.f) ? e : __fmul_rn(NEG_SLOPE, e);

    // row sum: strictly sequential in edge order
    float S = 0.f;
#pragma unroll
    for (int k = 0; k < DEG; k++)
        S = __fadd_rn(S, __shfl_sync(0xFFFFFFFFu, e, k));

    const float att = __fdiv_rn(e, S);
    const float wgt = __fmul_rn(nv[eidx], att);   // vals = nv * att

    cw[wid][lane] = make_float2(__int_as_float(col), wgt);
    __syncwarp();

    const u64* __restrict__ m2 = (const u64*)msg;  // packed col-pairs
    u64 acc = 0ull;
#pragma unroll
    for (int kb = 0; kb < DEG; kb += 8) {
        int c[8]; u64 w2[8];
#pragma unroll
        for (int i = 0; i < 8; i++) {
            const float2 t = cw[wid][kb + i];      // broadcast LDS.64
            c[i] = __float_as_int(t.x);
            w2[i] = packdup(t.y);
        }
        u64 m[8];
#pragma unroll
        for (int i = 0; i < 8; i++)
            m[i] = m2[(size_t)c[i] * (D / 2) + lane];
#pragma unroll
        for (int i = 0; i < 8; i++)
            acc = add2(acc, mul2(w2[i], m[i]));    // ascending edge order
    }
    float ax, ay; unpack2(acc, ax, ay);
    ax = fmaxf(ax, 0.f);
    ay = fmaxf(ay, 0.f);
    ((float2*)out)[(size_t)row * (D / 2) + lane] = make_float2(ax, ay);
}

// Scratch for intermediates (no cudaMalloc allowed)
__device__ float g_msg[N_CELLS * D];
__device__ float g_ns[N_CELLS];
__device__ float g_nd[N_CELLS];

extern "C" void kernel_launch(void* const* d_in, const int* in_sizes, int n_in,
                              void* d_out, int out_size) {
    const float* x    = (const float*)d_in[0];   // x_source [N,64]
    // d_in[1] = edge_rows (implicit: repeat(arange(N), 32)) — unused
    const int*   cols = (const int*)  d_in[2];   // edge_cols [N*32]
    const float* nv   = (const float*)d_in[3];   // neighborhood_values [N*32]
    const float* W0   = (const float*)d_in[4];   // [64,64]
    const float* a0   = (const float*)d_in[5];   // [128,1]
    float* out = (float*)d_out;

    float* msg; float* ns; float* nd;
    cudaGetSymbolAddress((void**)&msg, g_msg);
    cudaGetSymbolAddress((void**)&ns,  g_ns);
    cudaGetSymbolAddress((void**)&nd,  g_nd);

    const int n = N_CELLS;

    // Kernel 1: 64 rows per 64-thread CTA (thread-per-row), 782 CTAs
    int grid1 = (n + ROWS_CTA - 1) / ROWS_CTA;
    gemm_proj_kernel<<<grid1, 64>>>(x, W0, a0, msg, ns, nd, n);

    // Kernel 2: one warp per row, 8 rows per 256-thread block
    int grid2 = (n + 7) / 8;
    gat_aggregate_kernel<<<grid2, 256>>>(msg, ns, nd, cols, nv, out, n);
}